// round 3
// baseline (speedup 1.0000x reference)
#include <cuda_runtime.h>
#include <cuda_bf16.h>

#define N_NODES 50000
#define E_EDGES 800000
#define CIN_ 32
#define COUT_ 64
#define KK 25
#define RDIM 832   // 26 * 32  (25 spline kernels + 1 root slot)

// ---- scratch (static device globals; no allocation) ----
__device__ int    g_deg[N_NODES];
__device__ int    g_off[N_NODES + 1];
__device__ int    g_cursor[N_NODES];
__device__ float4 g_edata[E_EDGES];                    // {col, fx, fy, base} per CSR slot
__device__ float  g_z[(size_t)N_NODES * RDIM];         // 166 MB

// ---------------- CSR build ----------------
__global__ void k_zero_deg() {
    int i = blockIdx.x * blockDim.x + threadIdx.x;
    if (i < N_NODES) g_deg[i] = 0;
}

__global__ void k_hist(const int* __restrict__ ei) {
    int e = blockIdx.x * blockDim.x + threadIdx.x;
    if (e < E_EDGES) {
        int row = ei[e];
        row = min(max(row, 0), N_NODES - 1);   // defensive clamp
        atomicAdd(&g_deg[row], 1);
    }
}

__global__ __launch_bounds__(1024) void k_scan() {
    __shared__ int warp_sums[32];
    __shared__ int s_run;
    int tid = threadIdx.x, lane = tid & 31, wid = tid >> 5;
    if (tid == 0) s_run = 0;
    __syncthreads();
    for (int base = 0; base < N_NODES; base += 1024) {
        int i = base + tid;
        int v = (i < N_NODES) ? g_deg[i] : 0;
        int s = v;
        #pragma unroll
        for (int d = 1; d < 32; d <<= 1) {
            int t = __shfl_up_sync(0xffffffffu, s, d);
            if (lane >= d) s += t;
        }
        if (lane == 31) warp_sums[wid] = s;
        __syncthreads();
        if (wid == 0) {
            int ws = warp_sums[lane];
            #pragma unroll
            for (int d = 1; d < 32; d <<= 1) {
                int t = __shfl_up_sync(0xffffffffu, ws, d);
                if (lane >= d) ws += t;
            }
            warp_sums[lane] = ws;   // inclusive scan of warp totals
        }
        __syncthreads();
        int woff = wid ? warp_sums[wid - 1] : 0;
        int excl = s_run + woff + (s - v);
        if (i < N_NODES) { g_off[i] = excl; g_cursor[i] = excl; }
        __syncthreads();
        if (tid == 0) s_run += warp_sums[31];
        __syncthreads();
    }
    if (tid == 0) g_off[N_NODES] = s_run;
}

__global__ void k_scatter(const int* __restrict__ ei,
                          const float* __restrict__ pseudo) {
    int e = blockIdx.x * blockDim.x + threadIdx.x;
    if (e < E_EDGES) {
        int row = ei[e];
        int col = ei[E_EDGES + e];
        row = min(max(row, 0), N_NODES - 1);   // defensive clamp
        col = min(max(col, 0), N_NODES - 1);
        float vx = pseudo[2 * e]     * 4.0f;   // (KS - DEGREE) = 4
        float vy = pseudo[2 * e + 1] * 4.0f;
        float flx = floorf(vx), fly = floorf(vy);
        float fx = vx - flx, fy = vy - fly;
        int lox = min(max((int)flx, 0), 3);
        int loy = min(max((int)fly, 0), 3);
        int base = lox + 5 * loy;
        int pos = atomicAdd(&g_cursor[row], 1);
        g_edata[pos] = make_float4(__int_as_float(col), fx, fy, __int_as_float(base));
    }
}

// ---------------- per-node z accumulation (warp per node, no atomics) ----------------
__global__ __launch_bounds__(256) void k_accum(const float* __restrict__ x) {
    __shared__ float zsh[8][KK * 32];
    int w = threadIdx.x >> 5, lane = threadIdx.x & 31;
    int n = blockIdx.x * 8 + w;
    if (n >= N_NODES) return;

    #pragma unroll
    for (int j = lane; j < KK * 32; j += 32) zsh[w][j] = 0.0f;
    // per-lane ownership of zsh[w][*32+lane]: no sync needed within warp

    int start = g_off[n], end = g_off[n + 1];
    for (int e = start; e < end; ++e) {
        float4 ed = g_edata[e];                 // uniform broadcast load
        int   col  = __float_as_int(ed.x);
        float fx   = ed.y, fy = ed.z;
        int   base = __float_as_int(ed.w);
        float xv = x[col * CIN_ + lane];        // 128B coalesced random gather
        float gx = 1.0f - fx, gy = 1.0f - fy;
        zsh[w][(base    ) * 32 + lane] += gx * gy * xv;
        zsh[w][(base + 1) * 32 + lane] += fx * gy * xv;
        zsh[w][(base + 5) * 32 + lane] += gx * fy * xv;
        zsh[w][(base + 6) * 32 + lane] += fx * fy * xv;
    }

    float inv = 1.0f / fmaxf((float)(end - start), 1.0f);
    size_t zb = (size_t)n * RDIM;
    #pragma unroll
    for (int j = 0; j < KK; ++j)
        g_z[zb + j * 32 + lane] = zsh[w][j * 32 + lane] * inv;
    g_z[zb + KK * 32 + lane] = x[n * CIN_ + lane];   // root slot (unscaled)
}

// ---------------- out = z @ Wfull + bias ----------------
// Wfull[r][o] = (r < 800) ? weight[r*64+o] : root[(r-800)*64+o]
// tile: 128 nodes x 64 cols per block; thread = 4 nodes x 8 cols
__global__ __launch_bounds__(256) void k_gemm(const float* __restrict__ weight,
                                              const float* __restrict__ root,
                                              const float* __restrict__ bias,
                                              float* __restrict__ out) {
    __shared__ float wsh[64 * 64];
    __shared__ float zsh[128 * 65];   // pad 65 to break bank conflicts
    int tid = threadIdx.x;
    int n0 = blockIdx.x * 128;
    int cg = tid & 7, ng = tid >> 3;
    int o0 = cg * 8;

    float acc[4][8];
    #pragma unroll
    for (int a = 0; a < 4; ++a)
        #pragma unroll
        for (int j = 0; j < 8; ++j) acc[a][j] = bias[o0 + j];

    for (int ch = 0; ch < 13; ++ch) {
        int r0 = ch * 64;
        __syncthreads();
        for (int i = tid; i < 4096; i += 256) {
            int rr = i >> 6, o = i & 63;
            int r = r0 + rr;
            wsh[i] = (r < 800) ? weight[r * 64 + o] : root[(r - 800) * 64 + o];
        }
        for (int i = tid; i < 8192; i += 256) {
            int nl = i >> 6, rr = i & 63;
            int n = n0 + nl;
            zsh[nl * 65 + rr] = (n < N_NODES) ? g_z[(size_t)n * RDIM + r0 + rr] : 0.0f;
        }
        __syncthreads();
        #pragma unroll 8
        for (int rr = 0; rr < 64; ++rr) {
            float4 w0 = *(const float4*)&wsh[rr * 64 + o0];
            float4 w1 = *(const float4*)&wsh[rr * 64 + o0 + 4];
            float wv[8] = {w0.x, w0.y, w0.z, w0.w, w1.x, w1.y, w1.z, w1.w};
            float zv[4];
            zv[0] = zsh[(ng      ) * 65 + rr];
            zv[1] = zsh[(ng + 32) * 65 + rr];
            zv[2] = zsh[(ng + 64) * 65 + rr];
            zv[3] = zsh[(ng + 96) * 65 + rr];
            #pragma unroll
            for (int a = 0; a < 4; ++a)
                #pragma unroll
                for (int j = 0; j < 8; ++j)
                    acc[a][j] += zv[a] * wv[j];
        }
    }

    #pragma unroll
    for (int a = 0; a < 4; ++a) {
        int n = n0 + ng + a * 32;
        if (n < N_NODES) {
            float4 v0 = make_float4(acc[a][0], acc[a][1], acc[a][2], acc[a][3]);
            float4 v1 = make_float4(acc[a][4], acc[a][5], acc[a][6], acc[a][7]);
            *(float4*)&out[n * COUT_ + o0]     = v0;
            *(float4*)&out[n * COUT_ + o0 + 4] = v1;
        }
    }
}

// ---------------- launch ----------------
extern "C" void kernel_launch(void* const* d_in, const int* in_sizes, int n_in,
                              void* d_out, int out_size) {
    const float* x      = (const float*)d_in[0];
    const int*   ei     = (const int*)d_in[1];      // JAX x64-disabled: int32
    const float* pseudo = (const float*)d_in[2];
    const float* weight = (const float*)d_in[3];
    const float* root   = (const float*)d_in[4];
    const float* bias   = (const float*)d_in[5];
    float*       out    = (float*)d_out;

    k_zero_deg<<<(N_NODES + 255) / 256, 256>>>();
    k_hist    <<<(E_EDGES + 255) / 256, 256>>>(ei);
    k_scan    <<<1, 1024>>>();
    k_scatter <<<(E_EDGES + 255) / 256, 256>>>(ei, pseudo);
    k_accum   <<<(N_NODES + 7) / 8, 256>>>(x);
    k_gemm    <<<(N_NODES + 127) / 128, 256>>>(weight, root, bias, out);
}

// round 5
// speedup vs baseline: 1.5984x; 1.5984x over previous
#include <cuda_runtime.h>
#include <cuda_bf16.h>
#include <cstdint>

#define N_NODES 50000
#define E_EDGES 800000
#define CIN_ 32
#define COUT_ 64
#define KK 25
#define RDIM 832          // 26 * 32  (25 spline kernels + 1 root slot)
#define TILE_M 128
#define N_TILES ((N_NODES + TILE_M - 1) / TILE_M)   // 391
#define CHUNKS (RDIM / 32)                          // 26
#define PAD 36            // smem row pitch (floats): conflict-free fragment reads

// ---- scratch (static device globals; no allocation) ----
__device__ int    g_deg[N_NODES];
__device__ int    g_off[N_NODES + 1];
__device__ int    g_cursor[N_NODES];
__device__ float4 g_edata[E_EDGES];                  // {col, fx, fy, base} per CSR slot
__device__ float  g_z[(size_t)N_NODES * RDIM];       // 166 MB
__device__ float  g_wt_hi[COUT_ * RDIM];             // Wfull^T, tf32-hi part  [64][832]
__device__ float  g_wt_lo[COUT_ * RDIM];             // Wfull^T, residual      [64][832]

__device__ __forceinline__ float tf32_hi(float v) {
    return __uint_as_float(__float_as_uint(v) & 0xFFFFE000u);
}

// ---------------- CSR build ----------------
__global__ void k_zero_deg() {
    int i = blockIdx.x * blockDim.x + threadIdx.x;
    if (i < N_NODES) g_deg[i] = 0;
}

__global__ void k_hist(const int* __restrict__ ei) {
    int e = blockIdx.x * blockDim.x + threadIdx.x;
    if (e < E_EDGES) {
        int row = ei[e];
        row = min(max(row, 0), N_NODES - 1);
        atomicAdd(&g_deg[row], 1);
    }
}

__global__ __launch_bounds__(1024) void k_scan() {
    __shared__ int warp_sums[32];
    __shared__ int s_run;
    int tid = threadIdx.x, lane = tid & 31, wid = tid >> 5;
    if (tid == 0) s_run = 0;
    __syncthreads();
    for (int base = 0; base < N_NODES; base += 1024) {
        int i = base + tid;
        int v = (i < N_NODES) ? g_deg[i] : 0;
        int s = v;
        #pragma unroll
        for (int d = 1; d < 32; d <<= 1) {
            int t = __shfl_up_sync(0xffffffffu, s, d);
            if (lane >= d) s += t;
        }
        if (lane == 31) warp_sums[wid] = s;
        __syncthreads();
        if (wid == 0) {
            int ws = warp_sums[lane];
            #pragma unroll
            for (int d = 1; d < 32; d <<= 1) {
                int t = __shfl_up_sync(0xffffffffu, ws, d);
                if (lane >= d) ws += t;
            }
            warp_sums[lane] = ws;
        }
        __syncthreads();
        int woff = wid ? warp_sums[wid - 1] : 0;
        int excl = s_run + woff + (s - v);
        if (i < N_NODES) { g_off[i] = excl; g_cursor[i] = excl; }
        __syncthreads();
        if (tid == 0) s_run += warp_sums[31];
        __syncthreads();
    }
    if (tid == 0) g_off[N_NODES] = s_run;
}

__global__ void k_scatter(const int* __restrict__ ei,
                          const float* __restrict__ pseudo) {
    int e = blockIdx.x * blockDim.x + threadIdx.x;
    if (e < E_EDGES) {
        int row = ei[e];
        int col = ei[E_EDGES + e];
        row = min(max(row, 0), N_NODES - 1);
        col = min(max(col, 0), N_NODES - 1);
        float vx = pseudo[2 * e]     * 4.0f;   // (KS - DEGREE) = 4
        float vy = pseudo[2 * e + 1] * 4.0f;
        float flx = floorf(vx), fly = floorf(vy);
        float fx = vx - flx, fy = vy - fly;
        int lox = min(max((int)flx, 0), 3);
        int loy = min(max((int)fly, 0), 3);
        int base = lox + 5 * loy;
        int pos = atomicAdd(&g_cursor[row], 1);
        g_edata[pos] = make_float4(__int_as_float(col), fx, fy, __int_as_float(base));
    }
}

// Wfull^T split into tf32 hi/lo:  wt[o][r], r<800 -> weight[r][o], else root[r-800][o]
__global__ void k_prep_wt(const float* __restrict__ weight, const float* __restrict__ root) {
    int i = blockIdx.x * blockDim.x + threadIdx.x;   // i = o*832 + r
    if (i < COUT_ * RDIM) {
        int o = i / RDIM, r = i - o * RDIM;
        float w = (r < 800) ? weight[r * COUT_ + o] : root[(r - 800) * COUT_ + o];
        float hi = tf32_hi(w);
        g_wt_hi[i] = hi;
        g_wt_lo[i] = w - hi;
    }
}

// ---------------- per-node z accumulation (warp per node, no atomics) ----------------
__global__ __launch_bounds__(256) void k_accum(const float* __restrict__ x) {
    __shared__ float zsh[8][KK * 32];
    int w = threadIdx.x >> 5, lane = threadIdx.x & 31;
    int n = blockIdx.x * 8 + w;
    if (n >= N_NODES) return;

    #pragma unroll
    for (int j = lane; j < KK * 32; j += 32) zsh[w][j] = 0.0f;

    int start = g_off[n], end = g_off[n + 1];
    for (int e = start; e < end; ++e) {
        float4 ed = g_edata[e];
        int   col  = __float_as_int(ed.x);
        float fx   = ed.y, fy = ed.z;
        int   base = __float_as_int(ed.w);
        float xv = x[col * CIN_ + lane];
        float gx = 1.0f - fx, gy = 1.0f - fy;
        zsh[w][(base    ) * 32 + lane] += gx * gy * xv;
        zsh[w][(base + 1) * 32 + lane] += fx * gy * xv;
        zsh[w][(base + 5) * 32 + lane] += gx * fy * xv;
        zsh[w][(base + 6) * 32 + lane] += fx * fy * xv;
    }

    float inv = 1.0f / fmaxf((float)(end - start), 1.0f);
    size_t zb = (size_t)n * RDIM;
    #pragma unroll
    for (int j = 0; j < KK; ++j)
        g_z[zb + j * 32 + lane] = zsh[w][j * 32 + lane] * inv;
    g_z[zb + KK * 32 + lane] = x[n * CIN_ + lane];   // root slot (unscaled)
}

// ---------------- tensor-core GEMM via mma.sync (tf32, 2-term split) ----------------
// out[128 x 64] per block = z_tile[128 x 832] @ Wfull[832 x 64] + bias
// 8 warps; warp w owns rows [w*16, w*16+16), all 64 cols (8 n-tiles of m16n8k8).
// D += Ah*Bh + Ah*Bl + Al*Bh   (error ~2^-22)
// dynamic smem (floats): Ah[128*PAD] Al[128*PAD] Bh[64*PAD] Bl[64*PAD]
#define SM_AH 0
#define SM_AL (128 * PAD)
#define SM_BH (256 * PAD)
#define SM_BL (256 * PAD + 64 * PAD)
#define SM_FLOATS (256 * PAD + 128 * PAD)
#define SM_BYTES (SM_FLOATS * 4)

__device__ __forceinline__ void mma_tf32(float* c, const uint32_t* a, const uint32_t* b) {
    asm volatile(
        "mma.sync.aligned.m16n8k8.row.col.f32.tf32.tf32.f32 "
        "{%0,%1,%2,%3}, {%4,%5,%6,%7}, {%8,%9}, {%0,%1,%2,%3};"
        : "+f"(c[0]), "+f"(c[1]), "+f"(c[2]), "+f"(c[3])
        : "r"(a[0]), "r"(a[1]), "r"(a[2]), "r"(a[3]), "r"(b[0]), "r"(b[1]));
}

__global__ __launch_bounds__(256) void k_gemm_mma(const float* __restrict__ bias,
                                                  float* __restrict__ out) {
    extern __shared__ float sm[];
    int tid = threadIdx.x, w = tid >> 5, lane = tid & 31;
    int n0 = blockIdx.x * TILE_M;
    int qr = lane >> 2;          // quad row  (0..7)
    int qc = lane & 3;           // quad col  (0..3)

    float acc[8][4];
    #pragma unroll
    for (int nt = 0; nt < 8; ++nt)
        #pragma unroll
        for (int i = 0; i < 4; ++i) acc[nt][i] = 0.0f;

    for (int ch = 0; ch < CHUNKS; ++ch) {
        int r0 = ch * 32;
        __syncthreads();
        // stage A: 128 rows x 32 cols, hi/lo on the fly (1024 float4s)
        #pragma unroll
        for (int j = 0; j < 4; ++j) {
            int f4 = j * 256 + tid;
            int row = f4 >> 3, c4 = f4 & 7;
            int n = n0 + row;
            float4 v = make_float4(0.f, 0.f, 0.f, 0.f);
            if (n < N_NODES) v = *(const float4*)&g_z[(size_t)n * RDIM + r0 + c4 * 4];
            float4 hi = make_float4(tf32_hi(v.x), tf32_hi(v.y), tf32_hi(v.z), tf32_hi(v.w));
            float4 lo = make_float4(v.x - hi.x, v.y - hi.y, v.z - hi.z, v.w - hi.w);
            *(float4*)&sm[SM_AH + row * PAD + c4 * 4] = hi;
            *(float4*)&sm[SM_AL + row * PAD + c4 * 4] = lo;
        }
        // stage B: 64 o-rows x 32 r-cols, precomputed hi/lo (512 float4s)
        #pragma unroll
        for (int j = 0; j < 2; ++j) {
            int f4 = j * 256 + tid;
            int row = f4 >> 3, c4 = f4 & 7;
            float4 hi = *(const float4*)&g_wt_hi[row * RDIM + r0 + c4 * 4];
            float4 lo = *(const float4*)&g_wt_lo[row * RDIM + r0 + c4 * 4];
            *(float4*)&sm[SM_BH + row * PAD + c4 * 4] = hi;
            *(float4*)&sm[SM_BL + row * PAD + c4 * 4] = lo;
        }
        __syncthreads();

        #pragma unroll
        for (int k8 = 0; k8 < 4; ++k8) {
            int kb = k8 * 8;
            int ar0 = (w * 16 + qr) * PAD + kb + qc;       // rows qr, qr+8 ; cols qc, qc+4
            uint32_t ah[4], al[4];
            ah[0] = __float_as_uint(sm[SM_AH + ar0]);
            ah[1] = __float_as_uint(sm[SM_AH + ar0 + 8 * PAD]);
            ah[2] = __float_as_uint(sm[SM_AH + ar0 + 4]);
            ah[3] = __float_as_uint(sm[SM_AH + ar0 + 8 * PAD + 4]);
            al[0] = __float_as_uint(sm[SM_AL + ar0]);
            al[1] = __float_as_uint(sm[SM_AL + ar0 + 8 * PAD]);
            al[2] = __float_as_uint(sm[SM_AL + ar0 + 4]);
            al[3] = __float_as_uint(sm[SM_AL + ar0 + 8 * PAD + 4]);
            #pragma unroll
            for (int nt = 0; nt < 8; ++nt) {
                int bo = (nt * 8 + qr) * PAD + kb + qc;    // b0: k=qc, n=qr ; b1: k=qc+4
                uint32_t bh[2], bl[2];
                bh[0] = __float_as_uint(sm[SM_BH + bo]);
                bh[1] = __float_as_uint(sm[SM_BH + bo + 4]);
                bl[0] = __float_as_uint(sm[SM_BL + bo]);
                bl[1] = __float_as_uint(sm[SM_BL + bo + 4]);
                mma_tf32(acc[nt], ah, bh);
                mma_tf32(acc[nt], ah, bl);
                mma_tf32(acc[nt], al, bh);
            }
        }
    }

    // epilogue: c0,c1 -> (row, 2*qc), (row, 2*qc+1); c2,c3 -> row+8
    int rowa = n0 + w * 16 + qr;
    int rowb = rowa + 8;
    #pragma unroll
    for (int nt = 0; nt < 8; ++nt) {
        int col = nt * 8 + 2 * qc;
        float b0 = bias[col], b1 = bias[col + 1];
        if (rowa < N_NODES)
            *(float2*)&out[rowa * COUT_ + col] = make_float2(acc[nt][0] + b0, acc[nt][1] + b1);
        if (rowb < N_NODES)
            *(float2*)&out[rowb * COUT_ + col] = make_float2(acc[nt][2] + b0, acc[nt][3] + b1);
    }
}

// ---------------- launch ----------------
extern "C" void kernel_launch(void* const* d_in, const int* in_sizes, int n_in,
                              void* d_out, int out_size) {
    const float* x      = (const float*)d_in[0];
    const int*   ei     = (const int*)d_in[1];      // JAX x64-disabled: int32
    const float* pseudo = (const float*)d_in[2];
    const float* weight = (const float*)d_in[3];
    const float* root   = (const float*)d_in[4];
    const float* bias   = (const float*)d_in[5];
    float*       out    = (float*)d_out;

    static bool attr_done = false;
    if (!attr_done) {
        cudaFuncSetAttribute(k_gemm_mma, cudaFuncAttributeMaxDynamicSharedMemorySize, SM_BYTES);
        attr_done = true;
    }

    k_zero_deg<<<(N_NODES + 255) / 256, 256>>>();
    k_hist    <<<(E_EDGES + 255) / 256, 256>>>(ei);
    k_scan    <<<1, 1024>>>();
    k_scatter <<<(E_EDGES + 255) / 256, 256>>>(ei, pseudo);
    k_prep_wt <<<(COUT_ * RDIM + 255) / 256, 256>>>(weight, root);
    k_accum   <<<(N_NODES + 7) / 8, 256>>>(x);
    k_gemm_mma<<<N_TILES, 256, SM_BYTES>>>(bias, out);
}